// round 16
// baseline (speedup 1.0000x reference)
#include <cuda_runtime.h>
#include <math.h>

// ============================================================================
// PhasorTransformer, fully fused single kernel.
//
// zf[0] = e^{i w31[0]} * sum_t e^{i w00[t]} * r[t] * e^{i x[t]},
//   r = F(m1 .* F(m2 .* F(m3)))  (F = unnormalized DFT, F^T = F; ortho
//   scalings drop out of angle; asin(sin(.)) = exact triangular wrap).
//
// R16: ONE kernel. Each block builds r'' in its own smem via the R6-proven
// float Stockham (re-indexed: 512 threads, 2 butterflies/thread/stage), then
// runs the R13-proven dot loop (one row/warp, depth-2 x prefetch) reading r''
// directly from the final ping-pong buffer. Removes the separate precompute
// launch + inter-kernel gap (~8-10us of wall time) for ~2-3us of fully
// parallel per-block redundant precompute.
// ============================================================================

#define NFFT 2048
#define TPB 512
#define WPB (TPB / 32)

__device__ __forceinline__ void acc4(float4 xv, float4 rr, float4 ri,
                                     float& ax, float& ay) {
    float s, c;
    __sincosf(xv.x, &s, &c);
    ax = fmaf(rr.x, c, ax); ax = fmaf(-ri.x, s, ax);
    ay = fmaf(rr.x, s, ay); ay = fmaf( ri.x, c, ay);
    __sincosf(xv.y, &s, &c);
    ax = fmaf(rr.y, c, ax); ax = fmaf(-ri.y, s, ax);
    ay = fmaf(rr.y, s, ay); ay = fmaf( ri.y, c, ay);
    __sincosf(xv.z, &s, &c);
    ax = fmaf(rr.z, c, ax); ax = fmaf(-ri.z, s, ax);
    ay = fmaf(rr.z, s, ay); ay = fmaf( ri.z, c, ay);
    __sincosf(xv.w, &s, &c);
    ax = fmaf(rr.w, c, ax); ax = fmaf(-ri.w, s, ax);
    ay = fmaf(rr.w, s, ay); ay = fmaf( ri.w, c, ay);
}

__global__ void __launch_bounds__(TPB)
fused_kernel(const float* __restrict__ x, const float* __restrict__ w,
             float* __restrict__ out, int rows) {
    __shared__ __align__(16) float br[2][NFFT];
    __shared__ __align__(16) float bi[2][NFFT];
    __shared__ float twr[NFFT / 2];
    __shared__ float twi[NFFT / 2];
    const int tid = threadIdx.x;

    // ---------------- per-block precompute of r'' (R6 Stockham, 512 thr) ----
    // twiddles exp(-2*pi*i*k/2048), k < 1024
    for (int k = tid; k < NFFT / 2; k += TPB) {
        float a = -6.2831853071795864769f * (float)k / (float)NFFT;
        float s, c;
        sincosf(a, &s, &c);
        twr[k] = c;
        twi[k] = s;
    }
    // buffer 0 = m3 = exp(i(w21 + w30))
    for (int e = tid; e < NFFT; e += TPB) {
        float a = w[10240 + e] + w[12288 + e];
        float s, c;
        sincosf(a, &s, &c);
        br[0][e] = c;
        bi[0][e] = s;
    }
    __syncthreads();

    int cur = 0;
    for (int f = 0; f < 3; f++) {
        // 11 Stockham radix-2 stages, natural-order output
        for (int t = 0; t < 11; t++) {
            const int s = 1 << t;
            const int nxt = cur ^ 1;
            for (int n = tid; n < NFFT / 2; n += TPB) {
                const int p = n >> t;
                const int q = n & (s - 1);
                const int j0 = q + (p << (t + 1));
                const int j1 = j0 + s;
                float ar = br[cur][n],             ai = bi[cur][n];
                float crr = br[cur][n + NFFT / 2], cii = bi[cur][n + NFFT / 2];
                float sr = ar + crr, si = ai + cii;
                float dr = ar - crr, di = ai - cii;
                float wr = twr[p << t], wi = twi[p << t];
                float er = fmaf(dr, wr, -di * wi);
                float ei = fmaf(dr, wi,  di * wr);
                br[nxt][j0] = sr; bi[nxt][j0] = si;
                br[nxt][j1] = er; bi[nxt][j1] = ei;
            }
            cur = nxt;
            __syncthreads();
        }
        // inter-FFT phase multiply (f=0: m2, f=1: m1)
        if (f < 2) {
            const int o1 = (f == 0) ? 6144 : 2048;
            const int o2 = (f == 0) ? 8192 : 4096;
            for (int e = tid; e < NFFT; e += TPB) {
                float a = w[o1 + e] + w[o2 + e];
                float s, c;
                sincosf(a, &s, &c);
                float vr = br[cur][e], vi = bi[cur][e];
                br[cur][e] = fmaf(vr, c, -vi * s);
                bi[cur][e] = fmaf(vr, s,  vi * c);
            }
            __syncthreads();
        }
    }
    // fold exp(i*(w00[e] + w31[0])) in place -> r''
    {
        const float w310 = w[14336];
        for (int e = tid; e < NFFT; e += TPB) {
            float a = w[e] + w310;
            float s, c;
            sincosf(a, &s, &c);
            float vr = br[cur][e], vi = bi[cur][e];
            br[cur][e] = fmaf(vr, c, -vi * s);
            bi[cur][e] = fmaf(vr, s,  vi * c);
        }
    }
    __syncthreads();

    // ---------------- dot: S = sum_t r''[t] e^{i x[t]}  (R13 loop) ----------
    const int warp = tid >> 5;
    const int lane = tid & 31;
    const float4* sR4 = (const float4*)&br[cur][0];
    const float4* sI4 = (const float4*)&bi[cur][0];

    for (int row = blockIdx.x * WPB + warp; row < rows; row += gridDim.x * WPB) {
        const float4* xr = (const float4*)(x + (size_t)row * NFFT);
        float ax = 0.f, ay = 0.f;

        // 2-deep rotating prefetch of x; table reads stay in the loop body.
        float4 x0 = __ldg(&xr[lane]);
        float4 x1 = __ldg(&xr[lane + 32]);
#pragma unroll
        for (int j = 0; j < 16; j++) {
            float4 xn = (j < 14) ? __ldg(&xr[lane + 32 * (j + 2)]) : x0;
            int e4 = lane + 32 * j;
            float4 rr = sR4[e4];
            float4 ri = sI4[e4];
            acc4(x0, rr, ri, ax, ay);
            x0 = x1;
            x1 = xn;
        }
#pragma unroll
        for (int off = 16; off > 0; off >>= 1) {
            ax += __shfl_xor_sync(0xffffffffu, ax, off);
            ay += __shfl_xor_sync(0xffffffffu, ay, off);
        }
        if (lane == 0) {
            float th = atan2f(ay, ax);
            const float PI_F = 3.14159265358979323846f;
            const float HPI  = 1.57079632679489661923f;
            if (th >  HPI)      th =  PI_F - th;
            else if (th < -HPI) th = -PI_F - th;
            out[row] = th;
        }
    }
}

// ---------------------------------------------------------------- launch
extern "C" void kernel_launch(void* const* d_in, const int* in_sizes, int n_in,
                              void* d_out, int out_size) {
    const float* x = (const float*)d_in[0];
    const float* w = (const float*)d_in[1];
    float* out = (float*)d_out;
    const int rows = in_sizes[0] / NFFT;
    if (rows <= 0) return;

    int grid = (rows + WPB - 1) / WPB;     // one row per warp, single pass
    if (grid < 1) grid = 1;
    fused_kernel<<<grid, TPB>>>(x, w, out, rows);
}

// round 17
// speedup vs baseline: 1.9049x; 1.9049x over previous
#include <cuda_runtime.h>
#include <math.h>

// ============================================================================
// PhasorTransformer, linear-algebra collapsed form, POLAR dot.
//
// zf[0] = e^{i w31[0]} * sum_t e^{i w00[t]} * r[t] * e^{i x[t]},
//   r = F(m1 .* F(m2 .* F(m3)))  (F = unnormalized DFT, F^T = F).
// Write r'' = A e^{i phi} (phi absorbs w00[t] + w31[0]). Then per row:
//   S = sum_t A[t] e^{i(x[t] + phi[t])}
//   -> per element: 1 FADD + sincos + 2 FMA   (was 8 FMA in cartesian form).
//
// Kernel 1 = R6 float Stockham, publishes amplitude/phase tables.
// Kernel 2 = R13 dot shape (TPB 512, one row/warp, depth-2 x prefetch).
// ============================================================================

#define NFFT 2048

__device__ float g_amp[NFFT];
__device__ float g_phi[NFFT];

// ---------------------------------------------------------------- precompute
#define PRE_T 1024

__global__ void __launch_bounds__(PRE_T)
precompute_kernel(const float* __restrict__ w) {
    __shared__ float br[2][NFFT];
    __shared__ float bi[2][NFFT];
    __shared__ float twr[NFFT / 2];
    __shared__ float twi[NFFT / 2];
    const int tid = threadIdx.x;

    {   // twiddles exp(-2*pi*i*k/2048), k < 1024
        float a = -6.2831853071795864769f * (float)tid / (float)NFFT;
        float s, c;
        sincosf(a, &s, &c);
        twr[tid] = c;
        twi[tid] = s;
    }
    // buffer 0 = m3 = exp(i(w21 + w30))
#pragma unroll
    for (int k = 0; k < 2; k++) {
        int e = tid + PRE_T * k;
        float a = w[10240 + e] + w[12288 + e];
        float s, c;
        sincosf(a, &s, &c);
        br[0][e] = c;
        bi[0][e] = s;
    }
    __syncthreads();

    int cur = 0;
    for (int f = 0; f < 3; f++) {
        // 11 Stockham radix-2 stages, natural-order output, 1 butterfly/thread
        for (int t = 0; t < 11; t++) {
            const int s = 1 << t;
            const int nxt = cur ^ 1;
            const int n = tid;
            const int p = n >> t;
            const int q = n & (s - 1);
            const int j0 = q + (p << (t + 1));
            const int j1 = j0 + s;
            float ar = br[cur][n],             ai = bi[cur][n];
            float crr = br[cur][n + NFFT / 2], cii = bi[cur][n + NFFT / 2];
            float sr = ar + crr, si = ai + cii;
            float dr = ar - crr, di = ai - cii;
            float wr = twr[p << t], wi = twi[p << t];
            float er = fmaf(dr, wr, -di * wi);
            float ei = fmaf(dr, wi,  di * wr);
            br[nxt][j0] = sr; bi[nxt][j0] = si;
            br[nxt][j1] = er; bi[nxt][j1] = ei;
            cur = nxt;
            __syncthreads();
        }
        if (f < 2) {
            const int o1 = (f == 0) ? 6144 : 2048;
            const int o2 = (f == 0) ? 8192 : 4096;
#pragma unroll
            for (int k = 0; k < 2; k++) {
                int e = tid + PRE_T * k;
                float a = w[o1 + e] + w[o2 + e];
                float s, c;
                sincosf(a, &s, &c);
                float vr = br[cur][e], vi = bi[cur][e];
                br[cur][e] = fmaf(vr, c, -vi * s);
                bi[cur][e] = fmaf(vr, s,  vi * c);
            }
            __syncthreads();
        }
    }

    // publish polar form; fold (w00[e] + w31[0]) directly into phase
    const float w310 = w[14336];
#pragma unroll
    for (int k = 0; k < 2; k++) {
        int e = tid + PRE_T * k;
        float vr = br[cur][e], vi = bi[cur][e];
        g_amp[e] = sqrtf(fmaf(vr, vr, vi * vi));
        g_phi[e] = atan2f(vi, vr) + w[e] + w310;
    }
}

// ---------------------------------------------------------------- main kernel
// warp-per-row polar dot: S = sum_t A[t] e^{i(x[t]+phi[t])}
#define TPB 512
#define WPB (TPB / 32)

__device__ __forceinline__ void acc4p(float4 xv, float4 av, float4 pv,
                                      float& ax, float& ay) {
    float s, c;
    __sincosf(xv.x + pv.x, &s, &c);
    ax = fmaf(av.x, c, ax); ay = fmaf(av.x, s, ay);
    __sincosf(xv.y + pv.y, &s, &c);
    ax = fmaf(av.y, c, ax); ay = fmaf(av.y, s, ay);
    __sincosf(xv.z + pv.z, &s, &c);
    ax = fmaf(av.z, c, ax); ay = fmaf(av.z, s, ay);
    __sincosf(xv.w + pv.w, &s, &c);
    ax = fmaf(av.w, c, ax); ay = fmaf(av.w, s, ay);
}

__global__ void __launch_bounds__(TPB)
dot_kernel(const float* __restrict__ x, float* __restrict__ out, int rows) {
    __shared__ float sA[NFFT], sP[NFFT];
    const int tid = threadIdx.x;
    for (int i = tid; i < NFFT; i += TPB) {
        sA[i] = g_amp[i];
        sP[i] = g_phi[i];
    }
    __syncthreads();

    const int warp = tid >> 5;
    const int lane = tid & 31;
    const float4* sA4 = (const float4*)sA;
    const float4* sP4 = (const float4*)sP;

    for (int row = blockIdx.x * WPB + warp; row < rows; row += gridDim.x * WPB) {
        const float4* xr = (const float4*)(x + (size_t)row * NFFT);
        float ax = 0.f, ay = 0.f;

        // 2-deep rotating prefetch of x; table reads stay in the loop body.
        float4 x0 = __ldg(&xr[lane]);
        float4 x1 = __ldg(&xr[lane + 32]);
#pragma unroll
        for (int j = 0; j < 16; j++) {
            float4 xn = (j < 14) ? __ldg(&xr[lane + 32 * (j + 2)]) : x0;
            int e4 = lane + 32 * j;
            float4 av = sA4[e4];
            float4 pv = sP4[e4];
            acc4p(x0, av, pv, ax, ay);
            x0 = x1;
            x1 = xn;
        }
#pragma unroll
        for (int off = 16; off > 0; off >>= 1) {
            ax += __shfl_xor_sync(0xffffffffu, ax, off);
            ay += __shfl_xor_sync(0xffffffffu, ay, off);
        }
        if (lane == 0) {
            float th = atan2f(ay, ax);
            const float PI_F = 3.14159265358979323846f;
            const float HPI  = 1.57079632679489661923f;
            if (th >  HPI)      th =  PI_F - th;
            else if (th < -HPI) th = -PI_F - th;
            out[row] = th;
        }
    }
}

// ---------------------------------------------------------------- launch
extern "C" void kernel_launch(void* const* d_in, const int* in_sizes, int n_in,
                              void* d_out, int out_size) {
    const float* x = (const float*)d_in[0];
    const float* w = (const float*)d_in[1];
    float* out = (float*)d_out;
    const int rows = in_sizes[0] / NFFT;
    if (rows <= 0) return;

    precompute_kernel<<<1, PRE_T>>>(w);

    int grid = (rows + WPB - 1) / WPB;     // one row per warp
    if (grid < 1) grid = 1;
    dot_kernel<<<grid, TPB>>>(x, out, rows);
}